// round 2
// baseline (speedup 1.0000x reference)
#include <cuda_runtime.h>

#define D 64
#define NMAX 150016
#define LMAX 3

// Scratch (device globals: allocation-free per harness rules)
__device__ float g_ego[NMAX * D];                 // current (un-normalized) embeddings
__device__ float g_side[NMAX * D];                // SpMM accumulator
__device__ float g_all[NMAX * (LMAX + 1) * D];    // concat of [ego0, norm1, norm2, norm3]

// ---------------------------------------------------------------------------
// init: ego = concat(user_emb, item_emb); all[:,0:64] = ego; side = 0
// ---------------------------------------------------------------------------
__global__ void init_kernel(const float* __restrict__ ue,
                            const float* __restrict__ ie,
                            int n_user, int n) {
    int total = n * (D / 4);
    for (int i = blockIdx.x * blockDim.x + threadIdx.x; i < total;
         i += gridDim.x * blockDim.x) {
        int row = i >> 4;          // D/4 = 16 float4 per row
        int q = (i & 15) * 4;
        float4 v;
        if (row < n_user) v = *(const float4*)(ue + row * D + q);
        else              v = *(const float4*)(ie + (row - n_user) * D + q);
        *(float4*)&g_ego[row * D + q] = v;
        *(float4*)&g_all[row * ((LMAX + 1) * D) + q] = v;
        *(float4*)&g_side[row * D + q] = make_float4(0.f, 0.f, 0.f, 0.f);
    }
}

// ---------------------------------------------------------------------------
// SpMM: side[r] += val * ego[c]  (16 threads per edge, float4 each)
// ---------------------------------------------------------------------------
__global__ void spmm_kernel(const float* __restrict__ aval,
                            const int* __restrict__ arow,
                            const int* __restrict__ acol,
                            int E) {
    int idx = blockIdx.x * blockDim.x + threadIdx.x;
    int e = idx >> 4;
    if (e >= E) return;
    int q = (idx & 15) * 4;
    float v = __ldg(aval + e);
    int r = __ldg(arow + e);
    int c = __ldg(acol + e);
    float4 x = *(const float4*)&g_ego[c * D + q];
    float* dst = &g_side[r * D + q];
    atomicAdd(dst + 0, v * x.x);
    atomicAdd(dst + 1, v * x.y);
    atomicAdd(dst + 2, v * x.z);
    atomicAdd(dst + 3, v * x.w);
}

// ---------------------------------------------------------------------------
// Dense: ego_new = leaky(side@Wgc + bgc + (ego*side)@Wbi + bbi)
//        all[:, (k+1)*64:] = l2norm(ego_new); ego = ego_new; side = 0
// Block: 256 threads = 64 cols x 4 row-groups; 16 rows per block.
// Weight columns live in registers (64+64 per thread).
// ---------------------------------------------------------------------------
__global__ void __launch_bounds__(256, 1)
dense_kernel(const float* __restrict__ Wgc, const float* __restrict__ bgc,
             const float* __restrict__ Wbi, const float* __restrict__ bbi,
             int n, int layer) {
    __shared__ float s_s[16][68];   // side tile (pad keeps float4 alignment: 272B rows)
    __shared__ float s_p[16][68];   // ego*side tile
    __shared__ float s_o[16][68];   // output tile (for norm)
    __shared__ float s_rn[16];      // 1/norm per row

    int t = threadIdx.x;
    int j = t & 63;
    int rg = t >> 6;                // 0..3
    int row0 = blockIdx.x * 16;

    // Load weight columns into registers
    float wg[64], wb[64];
#pragma unroll
    for (int k = 0; k < 64; k++) {
        wg[k] = __ldg(Wgc + k * 64 + j);
        wb[k] = __ldg(Wbi + k * 64 + j);
    }
    float bias = __ldg(bgc + j) + __ldg(bbi + j);

    // Stage 16 rows of side and p = ego*side; zero side for next layer
    {
        int base = t * 4;           // 0..1023
        int r = base >> 6;
        int c = base & 63;
        int grow = row0 + r;
        float4 sv = make_float4(0.f, 0.f, 0.f, 0.f);
        float4 ev = sv;
        if (grow < n) {
            sv = *(const float4*)&g_side[grow * D + c];
            ev = *(const float4*)&g_ego[grow * D + c];
            *(float4*)&g_side[grow * D + c] = make_float4(0.f, 0.f, 0.f, 0.f);
        }
        *(float4*)&s_s[r][c] = sv;
        float4 pv = make_float4(sv.x * ev.x, sv.y * ev.y, sv.z * ev.z, sv.w * ev.w);
        *(float4*)&s_p[r][c] = pv;
    }
    __syncthreads();

    // Accumulate: 4 rows per thread, 4 partial sums per row (ILP)
    float a0[4], a1[4], a2[4], a3[4];
#pragma unroll
    for (int rr = 0; rr < 4; rr++) { a0[rr] = 0.f; a1[rr] = 0.f; a2[rr] = 0.f; a3[rr] = 0.f; }

#pragma unroll
    for (int k4 = 0; k4 < 16; k4++) {
#pragma unroll
        for (int rr = 0; rr < 4; rr++) {
            int r = rg * 4 + rr;
            float4 s4 = *(const float4*)&s_s[r][k4 * 4];
            float4 p4 = *(const float4*)&s_p[r][k4 * 4];
            a0[rr] += s4.x * wg[k4 * 4 + 0] + p4.x * wb[k4 * 4 + 0];
            a1[rr] += s4.y * wg[k4 * 4 + 1] + p4.y * wb[k4 * 4 + 1];
            a2[rr] += s4.z * wg[k4 * 4 + 2] + p4.z * wb[k4 * 4 + 2];
            a3[rr] += s4.w * wg[k4 * 4 + 3] + p4.w * wb[k4 * 4 + 3];
        }
    }

    float aout[4];
#pragma unroll
    for (int rr = 0; rr < 4; rr++) {
        int r = rg * 4 + rr;
        float a = bias + ((a0[rr] + a1[rr]) + (a2[rr] + a3[rr]));
        a = (a > 0.f) ? a : 0.2f * a;         // leaky_relu(0.2)
        aout[rr] = a;
        s_o[r][j] = a;
    }
    __syncthreads();

    // Row L2 norms: 16 threads per row
    {
        int r = t >> 4;
        int i = t & 15;
        float ss = 0.f;
#pragma unroll
        for (int q = 0; q < 4; q++) {
            float x = s_o[r][i + 16 * q];
            ss += x * x;
        }
#pragma unroll
        for (int off = 8; off > 0; off >>= 1)
            ss += __shfl_down_sync(0xffffffffu, ss, off, 16);
        if (i == 0) s_rn[r] = 1.f / fmaxf(sqrtf(ss), 1e-12f);
    }
    __syncthreads();

#pragma unroll
    for (int rr = 0; rr < 4; rr++) {
        int r = rg * 4 + rr;
        int grow = row0 + r;
        if (grow < n) {
            g_ego[grow * D + j] = aout[rr];
            g_all[grow * ((LMAX + 1) * D) + (layer + 1) * D + j] = aout[rr] * s_rn[r];
        }
    }
}

// ---------------------------------------------------------------------------
// Gather: out[0:B*256) = all[users], out[B*256:2B*256) = all[N_USER+items]
// ---------------------------------------------------------------------------
__global__ void gather_kernel(const int* __restrict__ users,
                              const int* __restrict__ items,
                              float* __restrict__ out,
                              int B, int n_user) {
    int i = blockIdx.x * blockDim.x + threadIdx.x;
    int stride = (LMAX + 1) * D / 4;   // 64 float4 per row
    int total = 2 * B * stride;
    if (i >= total) return;
    int which = (i >= B * stride) ? 1 : 0;
    int ii = i - which * B * stride;
    int b = ii / stride;
    int q = ii - b * stride;
    int row = which ? (n_user + __ldg(items + b)) : __ldg(users + b);
    ((float4*)out)[i] = *(const float4*)&g_all[row * ((LMAX + 1) * D) + q * 4];
}

// ---------------------------------------------------------------------------
extern "C" void kernel_launch(void* const* d_in, const int* in_sizes, int n_in,
                              void* d_out, int out_size) {
    const float* ue   = (const float*)d_in[0];
    const float* ie   = (const float*)d_in[1];
    const float* Wgc  = (const float*)d_in[2];
    const float* bgc  = (const float*)d_in[3];
    const float* Wbi  = (const float*)d_in[4];
    const float* bbi  = (const float*)d_in[5];
    const float* aval = (const float*)d_in[6];
    const int*   arow = (const int*)d_in[7];
    const int*   acol = (const int*)d_in[8];
    const int*   users = (const int*)d_in[9];
    const int*   items = (const int*)d_in[10];

    int n_user = in_sizes[0] / D;
    int n_item = in_sizes[1] / D;
    int n = n_user + n_item;
    int E = in_sizes[6];
    int B = in_sizes[9];
    int L = in_sizes[3] / D;
    if (L > LMAX) L = LMAX;

    {
        int total = n * (D / 4);
        int blocks = (total + 255) / 256;
        init_kernel<<<blocks, 256>>>(ue, ie, n_user, n);
    }

    for (int k = 0; k < L; k++) {
        long long tthreads = (long long)E * 16;
        int blocks = (int)((tthreads + 255) / 256);
        spmm_kernel<<<blocks, 256>>>(aval, arow, acol, E);

        int dblocks = (n + 15) / 16;
        dense_kernel<<<dblocks, 256>>>(Wgc + k * D * D, bgc + k * D,
                                       Wbi + k * D * D, bbi + k * D,
                                       n, k);
    }

    {
        int total = 2 * B * ((LMAX + 1) * D / 4);
        int blocks = (total + 255) / 256;
        gather_kernel<<<blocks, 256>>>(users, items, (float*)d_out, B, n_user);
    }
}

// round 3
// speedup vs baseline: 2.1487x; 2.1487x over previous
#include <cuda_runtime.h>

#define D 64
#define NMAX 150016
#define EMAX 4800000
#define LMAX 3

// Scratch (device globals: allocation-free per harness rules)
__device__ float g_ego[NMAX * D];                 // current (un-normalized) embeddings
__device__ float g_side[NMAX * D];                // SpMM result
__device__ float g_all[NMAX * (LMAX + 1) * D];    // concat of [ego0, norm1, norm2, norm3]
__device__ int   g_cnt[NMAX];                     // per-row edge counts
__device__ int   g_rowptr[NMAX + 1];              // CSR row pointers
__device__ int   g_rowcur[NMAX];                  // scatter cursors
__device__ float g_eval[EMAX];                    // edge values sorted by row
__device__ int   g_ecol[EMAX];                    // edge cols sorted by row

// ---------------------------------------------------------------------------
// init: ego = concat(user_emb, item_emb); all[:,0:64] = ego; cnt = 0
// ---------------------------------------------------------------------------
__global__ void init_kernel(const float* __restrict__ ue,
                            const float* __restrict__ ie,
                            int n_user, int n) {
    int total = n * (D / 4);
    for (int i = blockIdx.x * blockDim.x + threadIdx.x; i < total;
         i += gridDim.x * blockDim.x) {
        int row = i >> 4;          // 16 float4 per row
        int q = (i & 15) * 4;
        float4 v;
        if (row < n_user) v = *(const float4*)(ue + row * D + q);
        else              v = *(const float4*)(ie + (row - n_user) * D + q);
        *(float4*)&g_ego[row * D + q] = v;
        *(float4*)&g_all[row * ((LMAX + 1) * D) + q] = v;
        if (i < n) g_cnt[i] = 0;
    }
}

// ---------------------------------------------------------------------------
// CSR build step 1: histogram of row indices
// ---------------------------------------------------------------------------
__global__ void hist_kernel(const int* __restrict__ arow, int E) {
    int e = blockIdx.x * blockDim.x + threadIdx.x;
    if (e < E) atomicAdd(&g_cnt[__ldg(arow + e)], 1);
}

// ---------------------------------------------------------------------------
// CSR build step 2: exclusive scan (single block, 1024 threads)
// ---------------------------------------------------------------------------
__global__ void scan_kernel(int n, int E) {
    __shared__ int s[1024];
    int t = threadIdx.x;
    int chunk = (n + 1023) >> 10;
    int lo = t * chunk;
    int hi = min(lo + chunk, n);
    int sum = 0;
    for (int i = lo; i < hi; i++) sum += g_cnt[i];
    s[t] = sum;
    __syncthreads();
    for (int off = 1; off < 1024; off <<= 1) {
        int v = (t >= off) ? s[t - off] : 0;
        __syncthreads();
        s[t] += v;
        __syncthreads();
    }
    int run = (t == 0) ? 0 : s[t - 1];
    for (int i = lo; i < hi; i++) {
        g_rowptr[i] = run;
        g_rowcur[i] = run;
        run += g_cnt[i];
    }
    if (t == 0) g_rowptr[n] = E;
}

// ---------------------------------------------------------------------------
// CSR build step 3: scatter edges into row-sorted order
// ---------------------------------------------------------------------------
__global__ void scatter_kernel(const float* __restrict__ aval,
                               const int* __restrict__ arow,
                               const int* __restrict__ acol, int E) {
    int e = blockIdx.x * blockDim.x + threadIdx.x;
    if (e >= E) return;
    int r = __ldg(arow + e);
    int p = atomicAdd(&g_rowcur[r], 1);
    g_eval[p] = __ldg(aval + e);
    g_ecol[p] = __ldg(acol + e);
}

// ---------------------------------------------------------------------------
// SpMM (CSR, no atomics): side[r] = sum_j val_j * ego[col_j]
// 16 lanes per row; edges staged 16 at a time, broadcast via shfl(width=16).
// ---------------------------------------------------------------------------
__global__ void __launch_bounds__(256)
spmm_csr_kernel(int n) {
    int t = threadIdx.x;
    int lane = t & 15;
    int row = blockIdx.x * 16 + (t >> 4);
    if (row >= n) return;
    unsigned hm = 0xFFFFu << (t & 16);   // mask for this 16-lane half of the warp

    int start = __ldg(&g_rowptr[row]);
    int end   = __ldg(&g_rowptr[row + 1]);

    const float4* ego4 = (const float4*)g_ego;
    float4 acc = make_float4(0.f, 0.f, 0.f, 0.f);

    for (int base = start; base < end; base += 16) {
        int j = base + lane;
        float v = 0.f;
        int c = 0;
        if (j < end) {
            v = __ldg(&g_eval[j]);
            c = __ldg(&g_ecol[j]);
        }
        int m = min(16, end - base);
        for (int jj = 0; jj < m; jj++) {
            float vv = __shfl_sync(hm, v, jj, 16);
            int   cc = __shfl_sync(hm, c, jj, 16);
            float4 x = __ldg(&ego4[cc * 16 + lane]);
            acc.x += vv * x.x;
            acc.y += vv * x.y;
            acc.z += vv * x.z;
            acc.w += vv * x.w;
        }
    }
    ((float4*)g_side)[row * 16 + lane] = acc;
}

// ---------------------------------------------------------------------------
// Dense: ego_new = leaky(side@Wgc + bgc + (ego*side)@Wbi + bbi)
//        all[:, (k+1)*64:] = l2norm(ego_new); ego = ego_new
// Block: 256 threads = 64 cols x 4 row-groups; 64 rows per block
// (4 sub-tiles of 16 rows sharing register-resident weight columns).
// ---------------------------------------------------------------------------
__global__ void __launch_bounds__(256, 1)
dense_kernel(const float* __restrict__ Wgc, const float* __restrict__ bgc,
             const float* __restrict__ Wbi, const float* __restrict__ bbi,
             int n, int layer) {
    __shared__ float s_s[16][68];   // side tile
    __shared__ float s_p[16][68];   // ego*side tile
    __shared__ float s_o[16][68];   // output tile (for norm)
    __shared__ float s_rn[16];      // 1/norm per row

    int t = threadIdx.x;
    int j = t & 63;
    int rg = t >> 6;                // 0..3
    int row00 = blockIdx.x * 64;

    // Load weight columns into registers (once, reused for 4 sub-tiles)
    float wg[64], wb[64];
#pragma unroll
    for (int k = 0; k < 64; k++) {
        wg[k] = __ldg(Wgc + k * 64 + j);
        wb[k] = __ldg(Wbi + k * 64 + j);
    }
    float bias = __ldg(bgc + j) + __ldg(bbi + j);

    for (int sub = 0; sub < 4; sub++) {
        int row0 = row00 + sub * 16;

        // Stage 16 rows of side and p = ego*side
        {
            int base = t * 4;
            int r = base >> 6;
            int c = base & 63;
            int grow = row0 + r;
            float4 sv = make_float4(0.f, 0.f, 0.f, 0.f);
            float4 ev = sv;
            if (grow < n) {
                sv = *(const float4*)&g_side[grow * D + c];
                ev = *(const float4*)&g_ego[grow * D + c];
            }
            *(float4*)&s_s[r][c] = sv;
            float4 pv = make_float4(sv.x * ev.x, sv.y * ev.y, sv.z * ev.z, sv.w * ev.w);
            *(float4*)&s_p[r][c] = pv;
        }
        __syncthreads();

        // Accumulate: 4 rows per thread, 4 partial sums per row (ILP)
        float a0[4], a1[4], a2[4], a3[4];
#pragma unroll
        for (int rr = 0; rr < 4; rr++) { a0[rr] = 0.f; a1[rr] = 0.f; a2[rr] = 0.f; a3[rr] = 0.f; }

#pragma unroll
        for (int k4 = 0; k4 < 16; k4++) {
#pragma unroll
            for (int rr = 0; rr < 4; rr++) {
                int r = rg * 4 + rr;
                float4 s4 = *(const float4*)&s_s[r][k4 * 4];
                float4 p4 = *(const float4*)&s_p[r][k4 * 4];
                a0[rr] += s4.x * wg[k4 * 4 + 0] + p4.x * wb[k4 * 4 + 0];
                a1[rr] += s4.y * wg[k4 * 4 + 1] + p4.y * wb[k4 * 4 + 1];
                a2[rr] += s4.z * wg[k4 * 4 + 2] + p4.z * wb[k4 * 4 + 2];
                a3[rr] += s4.w * wg[k4 * 4 + 3] + p4.w * wb[k4 * 4 + 3];
            }
        }

        float aout[4];
#pragma unroll
        for (int rr = 0; rr < 4; rr++) {
            int r = rg * 4 + rr;
            float a = bias + ((a0[rr] + a1[rr]) + (a2[rr] + a3[rr]));
            a = (a > 0.f) ? a : 0.2f * a;     // leaky_relu(0.2)
            aout[rr] = a;
            s_o[r][j] = a;
        }
        __syncthreads();

        // Row L2 norms: 16 threads per row
        {
            int r = t >> 4;
            int i = t & 15;
            float ss = 0.f;
#pragma unroll
            for (int q = 0; q < 4; q++) {
                float x = s_o[r][i + 16 * q];
                ss += x * x;
            }
#pragma unroll
            for (int off = 8; off > 0; off >>= 1)
                ss += __shfl_down_sync(0xffffffffu, ss, off, 16);
            if (i == 0) s_rn[r] = 1.f / fmaxf(sqrtf(ss), 1e-12f);
        }
        __syncthreads();

#pragma unroll
        for (int rr = 0; rr < 4; rr++) {
            int r = rg * 4 + rr;
            int grow = row0 + r;
            if (grow < n) {
                g_ego[grow * D + j] = aout[rr];
                g_all[grow * ((LMAX + 1) * D) + (layer + 1) * D + j] = aout[rr] * s_rn[r];
            }
        }
        __syncthreads();   // protect tiles before next sub-iteration overwrites
    }
}

// ---------------------------------------------------------------------------
// Gather: out[0:B*256) = all[users], out[B*256:2B*256) = all[N_USER+items]
// ---------------------------------------------------------------------------
__global__ void gather_kernel(const int* __restrict__ users,
                              const int* __restrict__ items,
                              float* __restrict__ out,
                              int B, int n_user) {
    int i = blockIdx.x * blockDim.x + threadIdx.x;
    const int stride = (LMAX + 1) * D / 4;   // 64 float4 per row
    int total = 2 * B * stride;
    if (i >= total) return;
    int which = (i >= B * stride) ? 1 : 0;
    int ii = i - which * B * stride;
    int b = ii >> 6;
    int q = ii & 63;
    int row = which ? (n_user + __ldg(items + b)) : __ldg(users + b);
    ((float4*)out)[i] = *(const float4*)&g_all[row * ((LMAX + 1) * D) + q * 4];
}

// ---------------------------------------------------------------------------
extern "C" void kernel_launch(void* const* d_in, const int* in_sizes, int n_in,
                              void* d_out, int out_size) {
    const float* ue   = (const float*)d_in[0];
    const float* ie   = (const float*)d_in[1];
    const float* Wgc  = (const float*)d_in[2];
    const float* bgc  = (const float*)d_in[3];
    const float* Wbi  = (const float*)d_in[4];
    const float* bbi  = (const float*)d_in[5];
    const float* aval = (const float*)d_in[6];
    const int*   arow = (const int*)d_in[7];
    const int*   acol = (const int*)d_in[8];
    const int*   users = (const int*)d_in[9];
    const int*   items = (const int*)d_in[10];

    int n_user = in_sizes[0] / D;
    int n_item = in_sizes[1] / D;
    int n = n_user + n_item;
    int E = in_sizes[6];
    int B = in_sizes[9];
    int L = in_sizes[3] / D;
    if (L > LMAX) L = LMAX;

    {
        int total = n * (D / 4);
        init_kernel<<<(total + 255) / 256, 256>>>(ue, ie, n_user, n);
    }

    // Build CSR once (reused by all L spmm calls)
    hist_kernel<<<(E + 255) / 256, 256>>>(arow, E);
    scan_kernel<<<1, 1024>>>(n, E);
    scatter_kernel<<<(E + 255) / 256, 256>>>(aval, arow, acol, E);

    for (int k = 0; k < L; k++) {
        spmm_csr_kernel<<<(n + 15) / 16, 256>>>(n);
        dense_kernel<<<(n + 63) / 64, 256>>>(Wgc + k * D * D, bgc + k * D,
                                             Wbi + k * D * D, bbi + k * D,
                                             n, k);
    }

    {
        int total = 2 * B * ((LMAX + 1) * D / 4);
        gather_kernel<<<(total + 255) / 256, 256>>>(users, items, (float*)d_out, B, n_user);
    }
}

// round 4
// speedup vs baseline: 2.8540x; 1.3283x over previous
#include <cuda_runtime.h>

#define D 64
#define NMAX 150016
#define EMAX 4800000
#define LMAX 3
#define NBMAX 1024   // max scan blocks (NMAX/256 = 587)

// Scratch (device globals: allocation-free per harness rules)
__device__ float g_ego[NMAX * D];                 // current (un-normalized) embeddings
__device__ float g_side[NMAX * D];                // SpMM result
__device__ float g_all[NMAX * (LMAX + 1) * D];    // concat of [ego0, norm1, norm2, norm3]
__device__ int   g_cnt[NMAX];                     // per-row edge counts
__device__ int   g_rowptr[NMAX + 1];              // CSR row pointers
__device__ int   g_rowcur[NMAX];                  // scatter cursors
__device__ int2  g_edge[EMAX];                    // (val as int bits, col) sorted by row
__device__ int   g_bsum[NBMAX];                   // per-block count sums
__device__ int   g_boff[NBMAX];                   // exclusive block offsets

// ---------------------------------------------------------------------------
// init: ego = concat(user_emb, item_emb); all[:,0:64] = ego; cnt = 0
// ---------------------------------------------------------------------------
__global__ void init_kernel(const float* __restrict__ ue,
                            const float* __restrict__ ie,
                            int n_user, int n) {
    int total = n * (D / 4);
    for (int i = blockIdx.x * blockDim.x + threadIdx.x; i < total;
         i += gridDim.x * blockDim.x) {
        int row = i >> 4;          // 16 float4 per row
        int q = (i & 15) * 4;
        float4 v;
        if (row < n_user) v = *(const float4*)(ue + row * D + q);
        else              v = *(const float4*)(ie + (row - n_user) * D + q);
        *(float4*)&g_ego[row * D + q] = v;
        *(float4*)&g_all[row * ((LMAX + 1) * D) + q] = v;
        if (i < n) g_cnt[i] = 0;
    }
}

// ---------------------------------------------------------------------------
// CSR step 1: histogram of row indices
// ---------------------------------------------------------------------------
__global__ void hist_kernel(const int* __restrict__ arow, int E) {
    int e = blockIdx.x * blockDim.x + threadIdx.x;
    if (e < E) atomicAdd(&g_cnt[__ldg(arow + e)], 1);
}

// ---------------------------------------------------------------------------
// CSR step 2a: per-block sums of counts (256 counts per block)
// ---------------------------------------------------------------------------
__global__ void bsum_kernel(int n) {
    __shared__ int s[8];
    int i = blockIdx.x * 256 + threadIdx.x;
    int v = (i < n) ? g_cnt[i] : 0;
#pragma unroll
    for (int off = 16; off > 0; off >>= 1)
        v += __shfl_down_sync(0xffffffffu, v, off);
    if ((threadIdx.x & 31) == 0) s[threadIdx.x >> 5] = v;
    __syncthreads();
    if (threadIdx.x < 8) {
        int x = s[threadIdx.x];
#pragma unroll
        for (int off = 4; off > 0; off >>= 1)
            x += __shfl_down_sync(0xffu, x, off, 8);
        if (threadIdx.x == 0) g_bsum[blockIdx.x] = x;
    }
}

// ---------------------------------------------------------------------------
// CSR step 2b: single-block exclusive scan of block sums (nb <= 1024)
// ---------------------------------------------------------------------------
__global__ void bscan_kernel(int nb) {
    __shared__ int s[NBMAX];
    int t = threadIdx.x;
    int v = (t < nb) ? g_bsum[t] : 0;
    s[t] = v;
    __syncthreads();
    for (int off = 1; off < NBMAX; off <<= 1) {
        int x = (t >= off) ? s[t - off] : 0;
        __syncthreads();
        s[t] += x;
        __syncthreads();
    }
    if (t < nb) g_boff[t] = s[t] - v;   // exclusive
}

// ---------------------------------------------------------------------------
// CSR step 2c: per-block scan + global offset -> rowptr, rowcur
// ---------------------------------------------------------------------------
__global__ void rowptr_kernel(int n, int E) {
    __shared__ int s[256];
    int t = threadIdx.x;
    int i = blockIdx.x * 256 + t;
    int v = (i < n) ? g_cnt[i] : 0;
    s[t] = v;
    __syncthreads();
    for (int off = 1; off < 256; off <<= 1) {
        int x = (t >= off) ? s[t - off] : 0;
        __syncthreads();
        s[t] += x;
        __syncthreads();
    }
    if (i < n) {
        int p = g_boff[blockIdx.x] + s[t] - v;
        g_rowptr[i] = p;
        g_rowcur[i] = p;
    }
    if (i == 0) g_rowptr[n] = E;
}

// ---------------------------------------------------------------------------
// CSR step 3: scatter edges into row-sorted order (single int2 store)
// ---------------------------------------------------------------------------
__global__ void scatter_kernel(const float* __restrict__ aval,
                               const int* __restrict__ arow,
                               const int* __restrict__ acol, int E) {
    int e = blockIdx.x * blockDim.x + threadIdx.x;
    if (e >= E) return;
    int r = __ldg(arow + e);
    int p = atomicAdd(&g_rowcur[r], 1);
    g_edge[p] = make_int2(__float_as_int(__ldg(aval + e)), __ldg(acol + e));
}

// ---------------------------------------------------------------------------
// SpMM (CSR, no atomics, no shfl): side[r] = sum_j val_j * ego[col_j]
// 16 lanes per row; edge records read uniformly (HW broadcast), unroll x4.
// ---------------------------------------------------------------------------
__global__ void __launch_bounds__(256)
spmm_csr_kernel(int n) {
    int t = threadIdx.x;
    int lane = t & 15;
    int row = blockIdx.x * 16 + (t >> 4);
    if (row >= n) return;

    int start = __ldg(&g_rowptr[row]);
    int end   = __ldg(&g_rowptr[row + 1]);

    const float4* ego4 = (const float4*)g_ego;
    float4 a0 = make_float4(0.f, 0.f, 0.f, 0.f);
    float4 a1 = make_float4(0.f, 0.f, 0.f, 0.f);

    int j = start;
    for (; j + 4 <= end; j += 4) {
        int2 e0 = __ldg(&g_edge[j + 0]);
        int2 e1 = __ldg(&g_edge[j + 1]);
        int2 e2 = __ldg(&g_edge[j + 2]);
        int2 e3 = __ldg(&g_edge[j + 3]);
        float4 x0 = __ldg(&ego4[e0.y * 16 + lane]);
        float4 x1 = __ldg(&ego4[e1.y * 16 + lane]);
        float4 x2 = __ldg(&ego4[e2.y * 16 + lane]);
        float4 x3 = __ldg(&ego4[e3.y * 16 + lane]);
        float v0 = __int_as_float(e0.x), v1 = __int_as_float(e1.x);
        float v2 = __int_as_float(e2.x), v3 = __int_as_float(e3.x);
        a0.x += v0 * x0.x; a0.y += v0 * x0.y; a0.z += v0 * x0.z; a0.w += v0 * x0.w;
        a1.x += v1 * x1.x; a1.y += v1 * x1.y; a1.z += v1 * x1.z; a1.w += v1 * x1.w;
        a0.x += v2 * x2.x; a0.y += v2 * x2.y; a0.z += v2 * x2.z; a0.w += v2 * x2.w;
        a1.x += v3 * x3.x; a1.y += v3 * x3.y; a1.z += v3 * x3.z; a1.w += v3 * x3.w;
    }
    for (; j < end; j++) {
        int2 e = __ldg(&g_edge[j]);
        float v = __int_as_float(e.x);
        float4 x = __ldg(&ego4[e.y * 16 + lane]);
        a0.x += v * x.x; a0.y += v * x.y; a0.z += v * x.z; a0.w += v * x.w;
    }
    a0.x += a1.x; a0.y += a1.y; a0.z += a1.z; a0.w += a1.w;
    ((float4*)g_side)[row * 16 + lane] = a0;
}

// ---------------------------------------------------------------------------
// Dense: ego_new = leaky(side@Wgc + bgc + (ego*side)@Wbi + bbi)
//        all[:, (k+1)*64:] = l2norm(ego_new); ego = ego_new
// Block: 256 threads = 64 cols x 4 row-groups; 64 rows per block
// ---------------------------------------------------------------------------
__global__ void __launch_bounds__(256, 1)
dense_kernel(const float* __restrict__ Wgc, const float* __restrict__ bgc,
             const float* __restrict__ Wbi, const float* __restrict__ bbi,
             int n, int layer) {
    __shared__ float s_s[16][68];
    __shared__ float s_p[16][68];
    __shared__ float s_o[16][68];
    __shared__ float s_rn[16];

    int t = threadIdx.x;
    int j = t & 63;
    int rg = t >> 6;
    int row00 = blockIdx.x * 64;

    float wg[64], wb[64];
#pragma unroll
    for (int k = 0; k < 64; k++) {
        wg[k] = __ldg(Wgc + k * 64 + j);
        wb[k] = __ldg(Wbi + k * 64 + j);
    }
    float bias = __ldg(bgc + j) + __ldg(bbi + j);

    for (int sub = 0; sub < 4; sub++) {
        int row0 = row00 + sub * 16;
        {
            int base = t * 4;
            int r = base >> 6;
            int c = base & 63;
            int grow = row0 + r;
            float4 sv = make_float4(0.f, 0.f, 0.f, 0.f);
            float4 ev = sv;
            if (grow < n) {
                sv = *(const float4*)&g_side[grow * D + c];
                ev = *(const float4*)&g_ego[grow * D + c];
            }
            *(float4*)&s_s[r][c] = sv;
            float4 pv = make_float4(sv.x * ev.x, sv.y * ev.y, sv.z * ev.z, sv.w * ev.w);
            *(float4*)&s_p[r][c] = pv;
        }
        __syncthreads();

        float a0[4], a1[4], a2[4], a3[4];
#pragma unroll
        for (int rr = 0; rr < 4; rr++) { a0[rr] = 0.f; a1[rr] = 0.f; a2[rr] = 0.f; a3[rr] = 0.f; }

#pragma unroll
        for (int k4 = 0; k4 < 16; k4++) {
#pragma unroll
            for (int rr = 0; rr < 4; rr++) {
                int r = rg * 4 + rr;
                float4 s4 = *(const float4*)&s_s[r][k4 * 4];
                float4 p4 = *(const float4*)&s_p[r][k4 * 4];
                a0[rr] += s4.x * wg[k4 * 4 + 0] + p4.x * wb[k4 * 4 + 0];
                a1[rr] += s4.y * wg[k4 * 4 + 1] + p4.y * wb[k4 * 4 + 1];
                a2[rr] += s4.z * wg[k4 * 4 + 2] + p4.z * wb[k4 * 4 + 2];
                a3[rr] += s4.w * wg[k4 * 4 + 3] + p4.w * wb[k4 * 4 + 3];
            }
        }

        float aout[4];
#pragma unroll
        for (int rr = 0; rr < 4; rr++) {
            int r = rg * 4 + rr;
            float a = bias + ((a0[rr] + a1[rr]) + (a2[rr] + a3[rr]));
            a = (a > 0.f) ? a : 0.2f * a;
            aout[rr] = a;
            s_o[r][j] = a;
        }
        __syncthreads();

        {
            int r = t >> 4;
            int i = t & 15;
            float ss = 0.f;
#pragma unroll
            for (int q = 0; q < 4; q++) {
                float x = s_o[r][i + 16 * q];
                ss += x * x;
            }
#pragma unroll
            for (int off = 8; off > 0; off >>= 1)
                ss += __shfl_down_sync(0xffffffffu, ss, off, 16);
            if (i == 0) s_rn[r] = 1.f / fmaxf(sqrtf(ss), 1e-12f);
        }
        __syncthreads();

#pragma unroll
        for (int rr = 0; rr < 4; rr++) {
            int r = rg * 4 + rr;
            int grow = row0 + rr + rg * 4 - rr + rr;  // = row0 + rg*4 + rr
            grow = row0 + rg * 4 + rr;
            if (grow < n) {
                g_ego[grow * D + j] = aout[rr];
                g_all[grow * ((LMAX + 1) * D) + (layer + 1) * D + j] = aout[rr] * s_rn[r];
            }
        }
        __syncthreads();
    }
}

// ---------------------------------------------------------------------------
// Gather: out[0:B*256) = all[users], out[B*256:2B*256) = all[N_USER+items]
// ---------------------------------------------------------------------------
__global__ void gather_kernel(const int* __restrict__ users,
                              const int* __restrict__ items,
                              float* __restrict__ out,
                              int B, int n_user) {
    int i = blockIdx.x * blockDim.x + threadIdx.x;
    const int stride = (LMAX + 1) * D / 4;
    int total = 2 * B * stride;
    if (i >= total) return;
    int which = (i >= B * stride) ? 1 : 0;
    int ii = i - which * B * stride;
    int b = ii >> 6;
    int q = ii & 63;
    int row = which ? (n_user + __ldg(items + b)) : __ldg(users + b);
    ((float4*)out)[i] = *(const float4*)&g_all[row * ((LMAX + 1) * D) + q * 4];
}

// ---------------------------------------------------------------------------
extern "C" void kernel_launch(void* const* d_in, const int* in_sizes, int n_in,
                              void* d_out, int out_size) {
    const float* ue   = (const float*)d_in[0];
    const float* ie   = (const float*)d_in[1];
    const float* Wgc  = (const float*)d_in[2];
    const float* bgc  = (const float*)d_in[3];
    const float* Wbi  = (const float*)d_in[4];
    const float* bbi  = (const float*)d_in[5];
    const float* aval = (const float*)d_in[6];
    const int*   arow = (const int*)d_in[7];
    const int*   acol = (const int*)d_in[8];
    const int*   users = (const int*)d_in[9];
    const int*   items = (const int*)d_in[10];

    int n_user = in_sizes[0] / D;
    int n_item = in_sizes[1] / D;
    int n = n_user + n_item;
    int E = in_sizes[6];
    int B = in_sizes[9];
    int L = in_sizes[3] / D;
    if (L > LMAX) L = LMAX;

    {
        int total = n * (D / 4);
        init_kernel<<<(total + 255) / 256, 256>>>(ue, ie, n_user, n);
    }

    // Build CSR once (reused by all L spmm calls)
    int nb = (n + 255) / 256;
    hist_kernel<<<(E + 255) / 256, 256>>>(arow, E);
    bsum_kernel<<<nb, 256>>>(n);
    bscan_kernel<<<1, NBMAX>>>(nb);
    rowptr_kernel<<<nb, 256>>>(n, E);
    scatter_kernel<<<(E + 255) / 256, 256>>>(aval, arow, acol, E);

    for (int k = 0; k < L; k++) {
        spmm_csr_kernel<<<(n + 15) / 16, 256>>>(n);
        dense_kernel<<<(n + 63) / 64, 256>>>(Wgc + k * D * D, bgc + k * D,
                                             Wbi + k * D * D, bbi + k * D,
                                             n, k);
    }

    {
        int total = 2 * B * ((LMAX + 1) * D / 4);
        gather_kernel<<<(total + 255) / 256, 256>>>(users, items, (float*)d_out, B, n_user);
    }
}

// round 5
// speedup vs baseline: 2.8673x; 1.0047x over previous
#include <cuda_runtime.h>

#define D 64
#define NMAX 150016
#define EMAX 4800000
#define LMAX 3
#define NBMAX 1024   // max scan blocks (NMAX/256 = 587)

// Scratch (device globals: allocation-free per harness rules)
__device__ float g_ego[NMAX * D];                 // current (un-normalized) embeddings
__device__ float g_side[NMAX * D];                // SpMM result
__device__ float g_all[NMAX * (LMAX + 1) * D];    // concat of [ego0, norm1, norm2, norm3]
__device__ int   g_cnt[NMAX];                     // per-row edge counts
__device__ int   g_rowptr[NMAX + 1];              // CSR row pointers
__device__ int   g_rowcur[NMAX];                  // scatter cursors
__device__ int2  g_edge[EMAX];                    // (val bits, col) sorted by row
__device__ int   g_bsum[NBMAX];                   // per-block count sums
__device__ int   g_boff[NBMAX];                   // exclusive block offsets

// ---- packed f32x2 helpers ---------------------------------------------------
__device__ __forceinline__ void ffma2(unsigned long long& d,
                                      unsigned long long a,
                                      unsigned long long b) {
    asm("fma.rn.f32x2 %0, %1, %2, %0;" : "+l"(d) : "l"(a), "l"(b));
}
__device__ __forceinline__ unsigned long long pack2(float lo, float hi) {
    unsigned long long r;
    asm("mov.b64 %0, {%1, %2};" : "=l"(r) : "f"(lo), "f"(hi));
    return r;
}
__device__ __forceinline__ float2 unpack2(unsigned long long v) {
    float2 r;
    asm("mov.b64 {%0, %1}, %2;" : "=f"(r.x), "=f"(r.y) : "l"(v));
    return r;
}

// ---------------------------------------------------------------------------
// init: ego = concat(user_emb, item_emb); all[:,0:64] = ego; cnt = 0
// ---------------------------------------------------------------------------
__global__ void init_kernel(const float* __restrict__ ue,
                            const float* __restrict__ ie,
                            int n_user, int n) {
    int total = n * (D / 4);
    for (int i = blockIdx.x * blockDim.x + threadIdx.x; i < total;
         i += gridDim.x * blockDim.x) {
        int row = i >> 4;
        int q = (i & 15) * 4;
        float4 v;
        if (row < n_user) v = *(const float4*)(ue + row * D + q);
        else              v = *(const float4*)(ie + (row - n_user) * D + q);
        *(float4*)&g_ego[row * D + q] = v;
        *(float4*)&g_all[row * ((LMAX + 1) * D) + q] = v;
        if (i < n) g_cnt[i] = 0;
    }
}

// ---------------------------------------------------------------------------
// CSR step 1: histogram of row indices
// ---------------------------------------------------------------------------
__global__ void hist_kernel(const int* __restrict__ arow, int E) {
    int e = blockIdx.x * blockDim.x + threadIdx.x;
    if (e < E) atomicAdd(&g_cnt[__ldg(arow + e)], 1);
}

// ---------------------------------------------------------------------------
// CSR step 2a: per-block sums of counts
// ---------------------------------------------------------------------------
__global__ void bsum_kernel(int n) {
    __shared__ int s[8];
    int i = blockIdx.x * 256 + threadIdx.x;
    int v = (i < n) ? g_cnt[i] : 0;
#pragma unroll
    for (int off = 16; off > 0; off >>= 1)
        v += __shfl_down_sync(0xffffffffu, v, off);
    if ((threadIdx.x & 31) == 0) s[threadIdx.x >> 5] = v;
    __syncthreads();
    if (threadIdx.x < 8) {
        int x = s[threadIdx.x];
#pragma unroll
        for (int off = 4; off > 0; off >>= 1)
            x += __shfl_down_sync(0xffu, x, off, 8);
        if (threadIdx.x == 0) g_bsum[blockIdx.x] = x;
    }
}

// ---------------------------------------------------------------------------
// CSR step 2b: single-block exclusive scan of block sums
// ---------------------------------------------------------------------------
__global__ void bscan_kernel(int nb) {
    __shared__ int s[NBMAX];
    int t = threadIdx.x;
    int v = (t < nb) ? g_bsum[t] : 0;
    s[t] = v;
    __syncthreads();
    for (int off = 1; off < NBMAX; off <<= 1) {
        int x = (t >= off) ? s[t - off] : 0;
        __syncthreads();
        s[t] += x;
        __syncthreads();
    }
    if (t < nb) g_boff[t] = s[t] - v;
}

// ---------------------------------------------------------------------------
// CSR step 2c: per-block scan + global offset -> rowptr, rowcur
// ---------------------------------------------------------------------------
__global__ void rowptr_kernel(int n, int E) {
    __shared__ int s[256];
    int t = threadIdx.x;
    int i = blockIdx.x * 256 + t;
    int v = (i < n) ? g_cnt[i] : 0;
    s[t] = v;
    __syncthreads();
    for (int off = 1; off < 256; off <<= 1) {
        int x = (t >= off) ? s[t - off] : 0;
        __syncthreads();
        s[t] += x;
        __syncthreads();
    }
    if (i < n) {
        int p = g_boff[blockIdx.x] + s[t] - v;
        g_rowptr[i] = p;
        g_rowcur[i] = p;
    }
    if (i == 0) g_rowptr[n] = E;
}

// ---------------------------------------------------------------------------
// CSR step 3: scatter edges into row-sorted order
// ---------------------------------------------------------------------------
__global__ void scatter_kernel(const float* __restrict__ aval,
                               const int* __restrict__ arow,
                               const int* __restrict__ acol, int E) {
    int e = blockIdx.x * blockDim.x + threadIdx.x;
    if (e >= E) return;
    int r = __ldg(arow + e);
    int p = atomicAdd(&g_rowcur[r], 1);
    g_edge[p] = make_int2(__float_as_int(__ldg(aval + e)), __ldg(acol + e));
}

// ---------------------------------------------------------------------------
// SpMM (CSR, no atomics): side[r] = sum_j val_j * ego[col_j]
// 16 lanes per row; uniform edge reads (HW broadcast); software-pipelined:
// next 4 edge records prefetched while current 4 gathers are in flight.
// ---------------------------------------------------------------------------
__global__ void __launch_bounds__(256)
spmm_csr_kernel(int n) {
    int t = threadIdx.x;
    int lane = t & 15;
    int row = blockIdx.x * 16 + (t >> 4);
    if (row >= n) return;

    int start = __ldg(&g_rowptr[row]);
    int end   = __ldg(&g_rowptr[row + 1]);

    const float4* ego4 = (const float4*)g_ego;
    float4 a0 = make_float4(0.f, 0.f, 0.f, 0.f);
    float4 a1 = make_float4(0.f, 0.f, 0.f, 0.f);

    int j = start;
    if (j + 4 <= end) {
        // prologue: load first batch
        int2 e0 = __ldg(&g_edge[j + 0]);
        int2 e1 = __ldg(&g_edge[j + 1]);
        int2 e2 = __ldg(&g_edge[j + 2]);
        int2 e3 = __ldg(&g_edge[j + 3]);
        for (; j + 8 <= end; j += 4) {
            // prefetch next batch (independent of gathers below)
            int2 f0 = __ldg(&g_edge[j + 4]);
            int2 f1 = __ldg(&g_edge[j + 5]);
            int2 f2 = __ldg(&g_edge[j + 6]);
            int2 f3 = __ldg(&g_edge[j + 7]);
            float4 x0 = __ldg(&ego4[e0.y * 16 + lane]);
            float4 x1 = __ldg(&ego4[e1.y * 16 + lane]);
            float4 x2 = __ldg(&ego4[e2.y * 16 + lane]);
            float4 x3 = __ldg(&ego4[e3.y * 16 + lane]);
            float v0 = __int_as_float(e0.x), v1 = __int_as_float(e1.x);
            float v2 = __int_as_float(e2.x), v3 = __int_as_float(e3.x);
            a0.x += v0 * x0.x; a0.y += v0 * x0.y; a0.z += v0 * x0.z; a0.w += v0 * x0.w;
            a1.x += v1 * x1.x; a1.y += v1 * x1.y; a1.z += v1 * x1.z; a1.w += v1 * x1.w;
            a0.x += v2 * x2.x; a0.y += v2 * x2.y; a0.z += v2 * x2.z; a0.w += v2 * x2.w;
            a1.x += v3 * x3.x; a1.y += v3 * x3.y; a1.z += v3 * x3.z; a1.w += v3 * x3.w;
            e0 = f0; e1 = f1; e2 = f2; e3 = f3;
        }
        // epilogue for the in-flight batch
        {
            float4 x0 = __ldg(&ego4[e0.y * 16 + lane]);
            float4 x1 = __ldg(&ego4[e1.y * 16 + lane]);
            float4 x2 = __ldg(&ego4[e2.y * 16 + lane]);
            float4 x3 = __ldg(&ego4[e3.y * 16 + lane]);
            float v0 = __int_as_float(e0.x), v1 = __int_as_float(e1.x);
            float v2 = __int_as_float(e2.x), v3 = __int_as_float(e3.x);
            a0.x += v0 * x0.x; a0.y += v0 * x0.y; a0.z += v0 * x0.z; a0.w += v0 * x0.w;
            a1.x += v1 * x1.x; a1.y += v1 * x1.y; a1.z += v1 * x1.z; a1.w += v1 * x1.w;
            a0.x += v2 * x2.x; a0.y += v2 * x2.y; a0.z += v2 * x2.z; a0.w += v2 * x2.w;
            a1.x += v3 * x3.x; a1.y += v3 * x3.y; a1.z += v3 * x3.z; a1.w += v3 * x3.w;
            j += 4;
        }
    }
    for (; j < end; j++) {
        int2 e = __ldg(&g_edge[j]);
        float v = __int_as_float(e.x);
        float4 x = __ldg(&ego4[e.y * 16 + lane]);
        a0.x += v * x.x; a0.y += v * x.y; a0.z += v * x.z; a0.w += v * x.w;
    }
    a0.x += a1.x; a0.y += a1.y; a0.z += a1.z; a0.w += a1.w;
    ((float4*)g_side)[row * 16 + lane] = a0;
}

// ---------------------------------------------------------------------------
// Dense: ego_new = leaky(side@Wgc + bgc + (ego*side)@Wbi + bbi)
//        all[:, (k+1)*64:] = l2norm(ego_new); ego = ego_new
// Block: 256 threads = 64 cols x 4 row-groups; 64 rows per block.
// Inner product uses packed fma.rn.f32x2 (FFMA2): float4 SMEM loads leave
// (x,y)/(z,w) in aligned register pairs; weights pre-packed to 64-bit regs.
// ---------------------------------------------------------------------------
__global__ void __launch_bounds__(256, 1)
dense_kernel(const float* __restrict__ Wgc, const float* __restrict__ bgc,
             const float* __restrict__ Wbi, const float* __restrict__ bbi,
             int n, int layer) {
    __shared__ float s_s[16][68];
    __shared__ float s_p[16][68];
    __shared__ float s_o[16][68];
    __shared__ float s_rn[16];

    int t = threadIdx.x;
    int j = t & 63;
    int rg = t >> 6;
    int row00 = blockIdx.x * 64;

    // Pre-packed weight column pairs: wgp[2k] = (Wgc[4k',j] pairs)
    unsigned long long wgp[32], wbp[32];
#pragma unroll
    for (int k2 = 0; k2 < 32; k2++) {
        wgp[k2] = pack2(__ldg(Wgc + (2 * k2) * 64 + j), __ldg(Wgc + (2 * k2 + 1) * 64 + j));
        wbp[k2] = pack2(__ldg(Wbi + (2 * k2) * 64 + j), __ldg(Wbi + (2 * k2 + 1) * 64 + j));
    }
    float bias = __ldg(bgc + j) + __ldg(bbi + j);

    for (int sub = 0; sub < 4; sub++) {
        int row0 = row00 + sub * 16;
        {
            int base = t * 4;
            int r = base >> 6;
            int c = base & 63;
            int grow = row0 + r;
            float4 sv = make_float4(0.f, 0.f, 0.f, 0.f);
            float4 ev = sv;
            if (grow < n) {
                sv = *(const float4*)&g_side[grow * D + c];
                ev = *(const float4*)&g_ego[grow * D + c];
            }
            *(float4*)&s_s[r][c] = sv;
            float4 pv = make_float4(sv.x * ev.x, sv.y * ev.y, sv.z * ev.z, sv.w * ev.w);
            *(float4*)&s_p[r][c] = pv;
        }
        __syncthreads();

        // 8 packed accumulators: acc01[rr] = (a0,a1), acc23[rr] = (a2,a3)
        unsigned long long acc01[4], acc23[4];
#pragma unroll
        for (int rr = 0; rr < 4; rr++) { acc01[rr] = 0ULL; acc23[rr] = 0ULL; }

#pragma unroll
        for (int k4 = 0; k4 < 16; k4++) {
#pragma unroll
            for (int rr = 0; rr < 4; rr++) {
                int r = rg * 4 + rr;
                ulonglong2 s2 = *(const ulonglong2*)&s_s[r][k4 * 4];
                ulonglong2 p2 = *(const ulonglong2*)&s_p[r][k4 * 4];
                ffma2(acc01[rr], s2.x, wgp[2 * k4 + 0]);
                ffma2(acc23[rr], s2.y, wgp[2 * k4 + 1]);
                ffma2(acc01[rr], p2.x, wbp[2 * k4 + 0]);
                ffma2(acc23[rr], p2.y, wbp[2 * k4 + 1]);
            }
        }

        float aout[4];
#pragma unroll
        for (int rr = 0; rr < 4; rr++) {
            int r = rg * 4 + rr;
            float2 u = unpack2(acc01[rr]);
            float2 w = unpack2(acc23[rr]);
            float a = bias + ((u.x + u.y) + (w.x + w.y));
            a = (a > 0.f) ? a : 0.2f * a;     // leaky_relu(0.2)
            aout[rr] = a;
            s_o[r][j] = a;
        }
        __syncthreads();

        // Row L2 norms: 16 threads per row
        {
            int r = t >> 4;
            int i = t & 15;
            float ss = 0.f;
#pragma unroll
            for (int q = 0; q < 4; q++) {
                float x = s_o[r][i + 16 * q];
                ss += x * x;
            }
#pragma unroll
            for (int off = 8; off > 0; off >>= 1)
                ss += __shfl_down_sync(0xffffffffu, ss, off, 16);
            if (i == 0) s_rn[r] = 1.f / fmaxf(sqrtf(ss), 1e-12f);
        }
        __syncthreads();

#pragma unroll
        for (int rr = 0; rr < 4; rr++) {
            int r = rg * 4 + rr;
            int grow = row0 + r;
            if (grow < n) {
                g_ego[grow * D + j] = aout[rr];
                g_all[grow * ((LMAX + 1) * D) + (layer + 1) * D + j] = aout[rr] * s_rn[r];
            }
        }
        __syncthreads();
    }
}

// ---------------------------------------------------------------------------
// Gather: out[0:B*256) = all[users], out[B*256:2B*256) = all[N_USER+items]
// ---------------------------------------------------------------------------
__global__ void gather_kernel(const int* __restrict__ users,
                              const int* __restrict__ items,
                              float* __restrict__ out,
                              int B, int n_user) {
    int i = blockIdx.x * blockDim.x + threadIdx.x;
    const int stride = (LMAX + 1) * D / 4;
    int total = 2 * B * stride;
    if (i >= total) return;
    int which = (i >= B * stride) ? 1 : 0;
    int ii = i - which * B * stride;
    int b = ii >> 6;
    int q = ii & 63;
    int row = which ? (n_user + __ldg(items + b)) : __ldg(users + b);
    ((float4*)out)[i] = *(const float4*)&g_all[row * ((LMAX + 1) * D) + q * 4];
}

// ---------------------------------------------------------------------------
extern "C" void kernel_launch(void* const* d_in, const int* in_sizes, int n_in,
                              void* d_out, int out_size) {
    const float* ue   = (const float*)d_in[0];
    const float* ie   = (const float*)d_in[1];
    const float* Wgc  = (const float*)d_in[2];
    const float* bgc  = (const float*)d_in[3];
    const float* Wbi  = (const float*)d_in[4];
    const float* bbi  = (const float*)d_in[5];
    const float* aval = (const float*)d_in[6];
    const int*   arow = (const int*)d_in[7];
    const int*   acol = (const int*)d_in[8];
    const int*   users = (const int*)d_in[9];
    const int*   items = (const int*)d_in[10];

    int n_user = in_sizes[0] / D;
    int n_item = in_sizes[1] / D;
    int n = n_user + n_item;
    int E = in_sizes[6];
    int B = in_sizes[9];
    int L = in_sizes[3] / D;
    if (L > LMAX) L = LMAX;

    {
        int total = n * (D / 4);
        init_kernel<<<(total + 255) / 256, 256>>>(ue, ie, n_user, n);
    }

    // Build CSR once (reused by all L spmm calls)
    int nb = (n + 255) / 256;
    hist_kernel<<<(E + 255) / 256, 256>>>(arow, E);
    bsum_kernel<<<nb, 256>>>(n);
    bscan_kernel<<<1, NBMAX>>>(nb);
    rowptr_kernel<<<nb, 256>>>(n, E);
    scatter_kernel<<<(E + 255) / 256, 256>>>(aval, arow, acol, E);

    for (int k = 0; k < L; k++) {
        spmm_csr_kernel<<<(n + 15) / 16, 256>>>(n);
        dense_kernel<<<(n + 63) / 64, 256>>>(Wgc + k * D * D, bgc + k * D,
                                             Wbi + k * D * D, bbi + k * D,
                                             n, k);
    }

    {
        int total = 2 * B * ((LMAX + 1) * D / 4);
        gather_kernel<<<(total + 255) / 256, 256>>>(users, items, (float*)d_out, B, n_user);
    }
}